// round 11
// baseline (speedup 1.0000x reference)
#include <cuda_runtime.h>
#include <cuda_bf16.h>
#include <cstdint>
#include <cstddef>

#define NN 100000
#define NE 600000
#define NF 64
#define EF 16
#define EH 128
#define NSTEPS 6
#define NTILE (NE / 64)      // 9375
#define NBLK  296            // 2 CTAs x 148 SMs, persistent

// ---- scratch (device globals; no allocation allowed) ----
__device__ float g_P  [(size_t)NN * EH];   // nf@W1 + b1
__device__ float g_U1 [(size_t)NN * EH];   // nf@U1 + b1
__device__ float g_B  [(size_t)NE * EH];   // B' = P[from] + ef@W2 + b2 + b3
__device__ float g_G0 [(size_t)NE * EH];   // G ping
__device__ float g_G1 [(size_t)NE * EH];   // G pong
__device__ float g_T0 [(size_t)NN * EH];   // T ping
__device__ float g_T1 [(size_t)NN * EH];   // T pong
__device__ uint4 g_W3p[4096];              // W3^T fragment-packed (bh0,bh1,bl0,bl1)
__device__ uint4 g_U2p[4096];              // U2^T fragment-packed
__device__ float g_cb [EH];                // W2_b + W3_b

// ================= helpers =================
__device__ __forceinline__ void mma16(float* c, const uint32_t* a,
                                      uint32_t b0, uint32_t b1) {
    asm volatile(
        "mma.sync.aligned.m16n8k16.row.col.f32.bf16.bf16.f32 "
        "{%0,%1,%2,%3}, {%4,%5,%6,%7}, {%8,%9}, {%0,%1,%2,%3};"
        : "+f"(c[0]), "+f"(c[1]), "+f"(c[2]), "+f"(c[3])
        : "r"(a[0]), "r"(a[1]), "r"(a[2]), "r"(a[3]), "r"(b0), "r"(b1));
}

__device__ __forceinline__ void red4(float* p, float x, float y, float z, float w) {
    asm volatile("red.global.add.v4.f32 [%0], {%1, %2, %3, %4};"
                 :: "l"(p), "f"(x), "f"(y), "f"(z), "f"(w) : "memory");
}

// rn-split (used offline in prep only)
__device__ __forceinline__ void split2(float x, float y, uint32_t& hi, uint32_t& lo) {
    __nv_bfloat162 h = __floats2bfloat162_rn(x, y);
    float2 hf = __bfloat1622float2(h);
    __nv_bfloat162 l = __floats2bfloat162_rn(x - hf.x, y - hf.y);
    hi = *(uint32_t*)&h;
    lo = *(uint32_t*)&l;
}

// fast truncation split: hw = packed hi16(x),hi16(y); lw = bf16x2(residuals)
__device__ __forceinline__ void tsplit(float x, float y, uint32_t& hw, uint32_t& lw) {
    uint32_t xb = __float_as_uint(x), yb = __float_as_uint(y);
    hw = __byte_perm(xb, yb, 0x7632);
    float lx = x - __uint_as_float(xb & 0xFFFF0000u);
    float ly = y - __uint_as_float(yb & 0xFFFF0000u);
    __nv_bfloat162 l2 = __floats2bfloat162_rn(lx, ly);
    lw = *(uint32_t*)&l2;
}

// pack W3^T / U2^T into fragment uint4 layout + combined bias
__global__ void prep_all(const float* __restrict__ W3, const float* __restrict__ U2,
                         const float* __restrict__ W2b, const float* __restrict__ W3b,
                         uint4* __restrict__ W3p, uint4* __restrict__ U2p,
                         float* __restrict__ cb) {
    int b = blockIdx.x, tid = threadIdx.x;
    if (b < 32) {
        const float* W = (b < 16) ? W3 : U2;
        uint4* out = (b < 16) ? W3p : U2p;
        int idx = (b & 15) * 256 + tid;            // 0..4095
        int tig = idx & 3, gid = (idx >> 2) & 7, nt = (idx >> 5) & 3;
        int ks = (idx >> 7) & 7, wc = idx >> 10;
        int n = wc * 32 + nt * 8 + gid;
        int kw0 = ks * 8 + tig, kw1 = kw0 + 4;
        uint32_t bh0, bl0, bh1, bl1;
        split2(W[(2 * kw0) * 128 + n], W[(2 * kw0 + 1) * 128 + n], bh0, bl0);
        split2(W[(2 * kw1) * 128 + n], W[(2 * kw1 + 1) * 128 + n], bh1, bl1);
        out[idx] = make_uint4(bh0, bh1, bl0, bl1);
    } else if (b == 32) {
        if (tid < EH) cb[tid] = W2b[tid] + W3b[tid];
    }
}

// ============================================================
// Fused 3xBF16 MMA GEMM over edges — persistent, fragment-packed smem,
// smem-repacked epilogue with red.v4 / stg.v4.
// ============================================================
static constexpr int A_PLANE = 1024;               // uint4 per plane
static constexpr int W_OFF   = 2176;               // uint4 offset of W (A region = 34816 B)
static constexpr int C_STRIDE = 136;               // floats per row in C repack
static constexpr size_t SM_TOT = (size_t)(W_OFF + 4096) * 16;   // 100352 B

template <bool FIRST>
__device__ __forceinline__ void stage_row(
    int e, int ks, const float* __restrict__ Bp, const float* __restrict__ Tprev,
    const float* __restrict__ Gprev, const int* __restrict__ from,
    uint32_t* hw, uint32_t* lw)
{
    const float* bp = Bp + (size_t)e * EH + ks * 16;
    float4 b0 = *(const float4*)(bp + 0);
    float4 b1 = *(const float4*)(bp + 4);
    float4 b2 = *(const float4*)(bp + 8);
    float4 b3 = *(const float4*)(bp + 12);
    float v[16];
    if constexpr (FIRST) {
        v[0]=fmaxf(b0.x,0.f); v[1]=fmaxf(b0.y,0.f); v[2]=fmaxf(b0.z,0.f); v[3]=fmaxf(b0.w,0.f);
        v[4]=fmaxf(b1.x,0.f); v[5]=fmaxf(b1.y,0.f); v[6]=fmaxf(b1.z,0.f); v[7]=fmaxf(b1.w,0.f);
        v[8]=fmaxf(b2.x,0.f); v[9]=fmaxf(b2.y,0.f); v[10]=fmaxf(b2.z,0.f); v[11]=fmaxf(b2.w,0.f);
        v[12]=fmaxf(b3.x,0.f); v[13]=fmaxf(b3.y,0.f); v[14]=fmaxf(b3.z,0.f); v[15]=fmaxf(b3.w,0.f);
    } else {
        int u = __ldg(&from[e]);
        const float* tp = Tprev + (size_t)u * EH + ks * 16;
        const float* gp = Gprev + (size_t)(e ^ 1) * EH + ks * 16;
        float4 t0 = *(const float4*)(tp + 0);
        float4 t1 = *(const float4*)(tp + 4);
        float4 t2 = *(const float4*)(tp + 8);
        float4 t3 = *(const float4*)(tp + 12);
        float4 g0 = *(const float4*)(gp + 0);
        float4 g1 = *(const float4*)(gp + 4);
        float4 g2 = *(const float4*)(gp + 8);
        float4 g3 = *(const float4*)(gp + 12);
        v[0]=fmaxf(b0.x+t0.x-g0.x,0.f); v[1]=fmaxf(b0.y+t0.y-g0.y,0.f);
        v[2]=fmaxf(b0.z+t0.z-g0.z,0.f); v[3]=fmaxf(b0.w+t0.w-g0.w,0.f);
        v[4]=fmaxf(b1.x+t1.x-g1.x,0.f); v[5]=fmaxf(b1.y+t1.y-g1.y,0.f);
        v[6]=fmaxf(b1.z+t1.z-g1.z,0.f); v[7]=fmaxf(b1.w+t1.w-g1.w,0.f);
        v[8]=fmaxf(b2.x+t2.x-g2.x,0.f); v[9]=fmaxf(b2.y+t2.y-g2.y,0.f);
        v[10]=fmaxf(b2.z+t2.z-g2.z,0.f); v[11]=fmaxf(b2.w+t2.w-g2.w,0.f);
        v[12]=fmaxf(b3.x+t3.x-g3.x,0.f); v[13]=fmaxf(b3.y+t3.y-g3.y,0.f);
        v[14]=fmaxf(b3.z+t3.z-g3.z,0.f); v[15]=fmaxf(b3.w+t3.w-g3.w,0.f);
    }
#pragma unroll
    for (int j = 0; j < 8; ++j)
        tsplit(v[2 * j], v[2 * j + 1], hw[j], lw[j]);
}

template <bool FIRST, bool OUT>
__global__ void __launch_bounds__(256, 2)
gemm_fused(const float* __restrict__ Bp, const float* __restrict__ Tprev,
           const float* __restrict__ Gprev, const uint4* __restrict__ Wg,
           const int* __restrict__ from, const int* __restrict__ scat,
           const float* __restrict__ obias,
           float* __restrict__ Gout, float* __restrict__ Acc)
{
    extern __shared__ uint4 smem4[];
    uint4* AhP = smem4;
    uint4* AlP = smem4 + A_PLANE;
    uint4* Wp  = smem4 + W_OFF;
    float* Cs  = (float*)smem4;          // reuses A region after MMA

    const int tid = threadIdx.x;

    // ---- stage packed W once ----
#pragma unroll
    for (int i = 0; i < 16; ++i) Wp[tid + i * 256] = Wg[tid + i * 256];

    // staging item: (row pair, k-block)
    const int ksI   = tid & 7;
    const int pr    = tid >> 3;        // 0..31
    const int wrmtI = pr >> 3;         // 0..3
    const int gidI  = pr & 7;
    const int raL   = wrmtI * 16 + gidI;
    const int xrI   = ksI & 3;
    const int baseI = ((wrmtI * 8 + ksI) * 8 + gidI) * 4;

    const int wid = tid >> 5, lane = tid & 31;
    const int gid = lane >> 2, tig = lane & 3;
    const int wr = wid & 1, wc = wid >> 1;
    const int ar0 = wr * 32, cn0 = wc * 32;

    // epilogue item: one row (tid>>2), 8 column quads q0+4j
    const int erow = tid >> 2;
    const int q0   = tid & 3;

    float4 ob4[8];
    if constexpr (OUT) {
#pragma unroll
        for (int j = 0; j < 8; ++j)
            ob4[j] = *(const float4*)(obias + (q0 + 4 * j) * 4);
    }

    for (int t = blockIdx.x; t < NTILE; t += NBLK) {
        const int r0 = t * 64;
        __syncthreads();   // previous epilogue Cs reads done

        // ---- stage rows (raL, raL+8), k-block ksI ----
        uint32_t hwa[8], lwa[8], hwb[8], lwb[8];
        stage_row<FIRST>(r0 + raL,     ksI, Bp, Tprev, Gprev, from, hwa, lwa);
        stage_row<FIRST>(r0 + raL + 8, ksI, Bp, Tprev, Gprev, from, hwb, lwb);
#pragma unroll
        for (int q = 0; q < 4; ++q) {
            AhP[baseI + (q ^ xrI)] = make_uint4(hwa[q], hwb[q], hwa[q + 4], hwb[q + 4]);
            AlP[baseI + (q ^ xrI)] = make_uint4(lwa[q], lwb[q], lwa[q + 4], lwb[q + 4]);
        }
        __syncthreads();

        // ---- MMA ----
        float acc[2][4][4];
#pragma unroll
        for (int mt = 0; mt < 2; ++mt)
#pragma unroll
            for (int nt = 0; nt < 4; ++nt)
#pragma unroll
                for (int j = 0; j < 4; ++j) acc[mt][nt][j] = 0.f;

#pragma unroll
        for (int ks = 0; ks < 8; ++ks) {
            const int xr = ks & 3;
            uint4 a_h[2], a_l[2];
#pragma unroll
            for (int mt = 0; mt < 2; ++mt) {
                int ia = (((wr * 2 + mt) * 8 + ks) * 8 + gid) * 4 + (tig ^ xr);
                a_h[mt] = AhP[ia];
                a_l[mt] = AlP[ia];
            }
#pragma unroll
            for (int nt = 0; nt < 4; ++nt) {
                int iw = (((wc * 8 + ks) * 4 + nt) * 8 + gid) * 4 + tig;
                uint4 w4 = Wp[iw];
                // hi*hi + lo*hi + hi*lo  (3xBF16)
                mma16(acc[0][nt], (const uint32_t*)&a_h[0], w4.x, w4.y);
                mma16(acc[1][nt], (const uint32_t*)&a_h[1], w4.x, w4.y);
                mma16(acc[0][nt], (const uint32_t*)&a_l[0], w4.x, w4.y);
                mma16(acc[1][nt], (const uint32_t*)&a_l[1], w4.x, w4.y);
                mma16(acc[0][nt], (const uint32_t*)&a_h[0], w4.z, w4.w);
                mma16(acc[1][nt], (const uint32_t*)&a_h[1], w4.z, w4.w);
            }
        }
        __syncthreads();   // MMA smem reads done; A region now reusable as Cs

        // ---- repack accumulators into smem (STS.64, conflict-free) ----
#pragma unroll
        for (int mt = 0; mt < 2; ++mt)
#pragma unroll
            for (int half = 0; half < 2; ++half) {
                int row = ar0 + mt * 16 + gid + half * 8;
#pragma unroll
                for (int nt = 0; nt < 4; ++nt) {
                    int col = cn0 + nt * 8 + tig * 2;
                    *(float2*)(Cs + row * C_STRIDE + col) =
                        make_float2(acc[mt][nt][half * 2], acc[mt][nt][half * 2 + 1]);
                }
            }
        __syncthreads();

        // ---- emit: 1 row per thread, 8 quads; red.v4 + stg.v4 ----
        {
            const int r  = r0 + erow;
            const int sc = __ldg(&scat[r]);
            float* ap = Acc + (size_t)sc * EH;
            float* gp = Gout + (size_t)r * EH;
            const float* cp = Cs + erow * C_STRIDE;
#pragma unroll
            for (int j = 0; j < 8; ++j) {
                const int c = (q0 + 4 * j) * 4;
                float4 v = *(const float4*)(cp + c);
                if constexpr (OUT) {
                    v.x += ob4[j].x; v.y += ob4[j].y;
                    v.z += ob4[j].z; v.w += ob4[j].w;
                } else {
                    *(float4*)(gp + c) = v;
                }
                red4(ap + c, v.x, v.y, v.z, v.w);
            }
        }
    }
}

// ============================================================
// Scalar fp32 GEMM (small precompute GEMMs only)
// ============================================================
template <int KTOT, int EPI>
__global__ void __launch_bounds__(256)
gemm_tile(const float* __restrict__ A, const float* __restrict__ W,
          const float* __restrict__ bias, float* __restrict__ C, int M,
          const int* __restrict__ gidx, const float* __restrict__ gadd)
{
    constexpr int KC = (KTOT < 32) ? KTOT : 32;
    __shared__ float As[KC][132];
    __shared__ float Ws[KC][128];

    const int tid = threadIdx.x;
    const int tr  = tid >> 4;
    const int tc  = tid & 15;
    const int r0  = blockIdx.x * 128;

    float acc[8][8];
#pragma unroll
    for (int i = 0; i < 8; ++i)
#pragma unroll
        for (int j = 0; j < 8; ++j) acc[i][j] = 0.f;

    for (int kc0 = 0; kc0 < KTOT; kc0 += KC) {
        __syncthreads();
#pragma unroll
        for (int i = 0; i < KC / 8; ++i) {
            int f  = tid + i * 256;
            int r  = f / (KC / 4);
            int c4 = (f % (KC / 4)) * 4;
            float4 v = make_float4(0.f, 0.f, 0.f, 0.f);
            int gr = r0 + r;
            if (gr < M) v = *(const float4*)(A + (size_t)gr * KTOT + kc0 + c4);
            As[c4 + 0][r] = v.x; As[c4 + 1][r] = v.y;
            As[c4 + 2][r] = v.z; As[c4 + 3][r] = v.w;
        }
#pragma unroll
        for (int i = 0; i < KC / 8; ++i) {
            int f  = tid + i * 256;
            int kr = f >> 5;
            int c4 = (f & 31) * 4;
            *(float4*)(&Ws[kr][c4]) = *(const float4*)(W + (size_t)(kc0 + kr) * EH + c4);
        }
        __syncthreads();
#pragma unroll
        for (int k = 0; k < KC; ++k) {
            float a[8], w[8];
            *(float4*)&a[0] = *(const float4*)&As[k][tr * 8];
            *(float4*)&a[4] = *(const float4*)&As[k][tr * 8 + 4];
            *(float4*)&w[0] = *(const float4*)&Ws[k][tc * 8];
            *(float4*)&w[4] = *(const float4*)&Ws[k][tc * 8 + 4];
#pragma unroll
            for (int i = 0; i < 8; ++i)
#pragma unroll
                for (int j = 0; j < 8; ++j) acc[i][j] += a[i] * w[j];
        }
    }

    float bs[8];
#pragma unroll
    for (int j = 0; j < 8; ++j) bs[j] = bias[tc * 8 + j];

    const int c0 = tc * 8;
#pragma unroll
    for (int i = 0; i < 8; ++i) {
        int r = r0 + tr * 8 + i;
        if (r >= M) continue;
        if constexpr (EPI == 0) {
            float4 v0, v1;
            v0.x = acc[i][0] + bs[0]; v0.y = acc[i][1] + bs[1];
            v0.z = acc[i][2] + bs[2]; v0.w = acc[i][3] + bs[3];
            v1.x = acc[i][4] + bs[4]; v1.y = acc[i][5] + bs[5];
            v1.z = acc[i][6] + bs[6]; v1.w = acc[i][7] + bs[7];
            *(float4*)(C + (size_t)r * EH + c0)     = v0;
            *(float4*)(C + (size_t)r * EH + c0 + 4) = v1;
        } else {
            int u = gidx[r];
            const float* gp = gadd + (size_t)u * EH + c0;
            float4 p0 = *(const float4*)gp;
            float4 p1 = *(const float4*)(gp + 4);
            float4 v0, v1;
            v0.x = acc[i][0] + bs[0] + p0.x; v0.y = acc[i][1] + bs[1] + p0.y;
            v0.z = acc[i][2] + bs[2] + p0.z; v0.w = acc[i][3] + bs[3] + p0.w;
            v1.x = acc[i][4] + bs[4] + p1.x; v1.y = acc[i][5] + bs[5] + p1.y;
            v1.z = acc[i][6] + bs[6] + p1.z; v1.w = acc[i][7] + bs[7] + p1.w;
            *(float4*)(C + (size_t)r * EH + c0)     = v0;
            *(float4*)(C + (size_t)r * EH + c0 + 4) = v1;
        }
    }
}

// out = relu(out + U1x)
__global__ void __launch_bounds__(256)
final_relu(float* __restrict__ out, const float* __restrict__ U1x)
{
    int idx = blockIdx.x * blockDim.x + threadIdx.x;
    if (idx >= NN * EH / 4) return;
    float4 a = ((const float4*)out)[idx];
    float4 b = ((const float4*)U1x)[idx];
    float4 r;
    r.x = fmaxf(a.x + b.x, 0.f);
    r.y = fmaxf(a.y + b.y, 0.f);
    r.z = fmaxf(a.z + b.z, 0.f);
    r.w = fmaxf(a.w + b.w, 0.f);
    ((float4*)out)[idx] = r;
}

extern "C" void kernel_launch(void* const* d_in, const int* in_sizes, int n_in,
                              void* d_out, int out_size)
{
    const float* nf  = (const float*)d_in[0];
    const float* ef  = (const float*)d_in[1];
    const int*   edg = (const int*)  d_in[3];
    const float* W1w = (const float*)d_in[4];
    const float* W1b = (const float*)d_in[5];
    const float* W2w = (const float*)d_in[6];
    const float* W2b = (const float*)d_in[7];
    const float* W3w = (const float*)d_in[8];
    const float* W3b = (const float*)d_in[9];
    const float* U1w = (const float*)d_in[10];
    const float* U1b = (const float*)d_in[11];
    const float* U2w = (const float*)d_in[12];
    const float* U2b = (const float*)d_in[13];

    const int* from = edg;
    const int* to   = edg + NE;

    float *P, *U1x, *B, *G0, *G1, *T0, *T1, *cb;
    uint4 *W3p, *U2p;
    cudaGetSymbolAddress((void**)&P,   g_P);
    cudaGetSymbolAddress((void**)&U1x, g_U1);
    cudaGetSymbolAddress((void**)&B,   g_B);
    cudaGetSymbolAddress((void**)&G0,  g_G0);
    cudaGetSymbolAddress((void**)&G1,  g_G1);
    cudaGetSymbolAddress((void**)&T0,  g_T0);
    cudaGetSymbolAddress((void**)&T1,  g_T1);
    cudaGetSymbolAddress((void**)&W3p, g_W3p);
    cudaGetSymbolAddress((void**)&U2p, g_U2p);
    cudaGetSymbolAddress((void**)&cb,  g_cb);

    cudaFuncSetAttribute(gemm_fused<true,  false>,
                         cudaFuncAttributeMaxDynamicSharedMemorySize, (int)SM_TOT);
    cudaFuncSetAttribute(gemm_fused<false, false>,
                         cudaFuncAttributeMaxDynamicSharedMemorySize, (int)SM_TOT);
    cudaFuncSetAttribute(gemm_fused<false, true>,
                         cudaFuncAttributeMaxDynamicSharedMemorySize, (int)SM_TOT);

    const int gnode = (NN + 127) / 128;
    const int gedge128 = (NE + 127) / 128;

    // weight prep + combined bias (single launch)
    prep_all<<<33, 256>>>(W3w, U2w, W2b, W3b, W3p, U2p, cb);

    // loop-invariant precomputes
    gemm_tile<64, 0><<<gnode, 256>>>(nf, W1w, W1b, P,   NN, nullptr, nullptr);
    gemm_tile<64, 0><<<gnode, 256>>>(nf, U1w, U1b, U1x, NN, nullptr, nullptr);
    gemm_tile<16, 1><<<gedge128, 256>>>(ef, W2w, cb, B, NE, from, P);

    // buffers: step s output lives in buffer (s & 1)
    float* Gb[2] = {G0, G1};
    float* Tb[2] = {T0, T1};

    // s = 1: h1 = relu(B'), G = h1@W3, T = seg(G, from)  -> buffer 1
    cudaMemsetAsync(Tb[1], 0, (size_t)NN * EH * sizeof(float));
    gemm_fused<true, false><<<NBLK, 256, SM_TOT>>>(
        B, nullptr, nullptr, W3p, from, from, nullptr, Gb[1], Tb[1]);

    // s = 2..5: read buffer (s-1)&1, write buffer s&1
    for (int s = 2; s <= 5; ++s) {
        cudaMemsetAsync(Tb[s & 1], 0, (size_t)NN * EH * sizeof(float));
        gemm_fused<false, false><<<NBLK, 256, SM_TOT>>>(
            B, Tb[(s - 1) & 1], Gb[(s - 1) & 1], W3p, from, from, nullptr,
            Gb[s & 1], Tb[s & 1]);
    }

    // readout: h6 built on the fly from (T5, G5) = buffer 1; red into d_out by `to`
    cudaMemsetAsync(d_out, 0, (size_t)NN * EH * sizeof(float));
    gemm_fused<false, true><<<NBLK, 256, SM_TOT>>>(
        B, Tb[1], Gb[1], U2p, from, to, U2b, nullptr, (float*)d_out);

    final_relu<<<(NN * EH / 4 + 255) / 256, 256>>>((float*)d_out, U1x);
}

// round 12
// speedup vs baseline: 1.2365x; 1.2365x over previous
#include <cuda_runtime.h>
#include <cuda_bf16.h>
#include <cstdint>
#include <cstddef>

#define NN 100000
#define NE 600000
#define NF 64
#define EF 16
#define EH 128
#define NSTEPS 6
#define NTILE (NE / 64)      // 9375
#define NBLK  296            // 2 CTAs x 148 SMs, persistent

// ---- scratch (device globals; no allocation allowed) ----
__device__ float g_P  [(size_t)NN * EH];   // nf@W1 + b1
__device__ float g_U1 [(size_t)NN * EH];   // nf@U1 + b1
__device__ float g_B  [(size_t)NE * EH];   // B' = P[from] + ef@W2 + b2 + b3
__device__ float g_G0 [(size_t)NE * EH];   // G ping
__device__ float g_G1 [(size_t)NE * EH];   // G pong
__device__ float g_T0 [(size_t)NN * EH];   // T buffers (3-way rotation)
__device__ float g_T1 [(size_t)NN * EH];
__device__ float g_T2 [(size_t)NN * EH];
__device__ uint4 g_W3p[4096];              // W3^T fragment-packed (bh0,bh1,bl0,bl1)
__device__ uint4 g_U2p[4096];              // U2^T fragment-packed
__device__ float g_cb [EH];                // W2_b + W3_b

// ================= helpers =================
__device__ __forceinline__ void mma16(float* c, const uint32_t* a,
                                      uint32_t b0, uint32_t b1) {
    asm volatile(
        "mma.sync.aligned.m16n8k16.row.col.f32.bf16.bf16.f32 "
        "{%0,%1,%2,%3}, {%4,%5,%6,%7}, {%8,%9}, {%0,%1,%2,%3};"
        : "+f"(c[0]), "+f"(c[1]), "+f"(c[2]), "+f"(c[3])
        : "r"(a[0]), "r"(a[1]), "r"(a[2]), "r"(a[3]), "r"(b0), "r"(b1));
}

__device__ __forceinline__ void red2(float* p, float x, float y) {
    asm volatile("red.global.add.v2.f32 [%0], {%1, %2};"
                 :: "l"(p), "f"(x), "f"(y) : "memory");
}

// rn-split (used offline in prep only)
__device__ __forceinline__ void split2(float x, float y, uint32_t& hi, uint32_t& lo) {
    __nv_bfloat162 h = __floats2bfloat162_rn(x, y);
    float2 hf = __bfloat1622float2(h);
    __nv_bfloat162 l = __floats2bfloat162_rn(x - hf.x, y - hf.y);
    hi = *(uint32_t*)&h;
    lo = *(uint32_t*)&l;
}

// fast truncation split: hw = packed hi16(x),hi16(y); lw = bf16x2(residuals)
__device__ __forceinline__ void tsplit(float x, float y, uint32_t& hw, uint32_t& lw) {
    uint32_t xb = __float_as_uint(x), yb = __float_as_uint(y);
    hw = __byte_perm(xb, yb, 0x7632);
    float lx = x - __uint_as_float(xb & 0xFFFF0000u);
    float ly = y - __uint_as_float(yb & 0xFFFF0000u);
    __nv_bfloat162 l2 = __floats2bfloat162_rn(lx, ly);
    lw = *(uint32_t*)&l2;
}

// pack W3^T / U2^T into fragment uint4 layout + combined bias
__global__ void prep_all(const float* __restrict__ W3, const float* __restrict__ U2,
                         const float* __restrict__ W2b, const float* __restrict__ W3b,
                         uint4* __restrict__ W3p, uint4* __restrict__ U2p,
                         float* __restrict__ cb) {
    int b = blockIdx.x, tid = threadIdx.x;
    if (b < 32) {
        const float* W = (b < 16) ? W3 : U2;
        uint4* out = (b < 16) ? W3p : U2p;
        int idx = (b & 15) * 256 + tid;            // 0..4095
        int tig = idx & 3, gid = (idx >> 2) & 7, nt = (idx >> 5) & 3;
        int ks = (idx >> 7) & 7, wc = idx >> 10;
        int n = wc * 32 + nt * 8 + gid;
        int kw0 = ks * 8 + tig, kw1 = kw0 + 4;
        uint32_t bh0, bl0, bh1, bl1;
        split2(W[(2 * kw0) * 128 + n], W[(2 * kw0 + 1) * 128 + n], bh0, bl0);
        split2(W[(2 * kw1) * 128 + n], W[(2 * kw1 + 1) * 128 + n], bh1, bl1);
        out[idx] = make_uint4(bh0, bh1, bl0, bl1);
    } else if (b == 32) {
        if (tid < EH) cb[tid] = W2b[tid] + W3b[tid];
    }
}

// ============================================================
// Fused 3xBF16 MMA GEMM over edges — persistent, fragment-packed smem.
// (R10 structure: per-warp epilogue, red.v2.)  Extra: Zbuf grid-stride
// zeroing at kernel end (prepares next step's T buffer / d_out).
// ============================================================
static constexpr int A_PLANE = 1024;               // uint4 per plane
static constexpr int W_OFF   = 2048;               // uint4 offset of W
static constexpr size_t SM_TOT = (size_t)(2048 + 4096) * 16;   // 98304 B

template <bool FIRST>
__device__ __forceinline__ void stage_row(
    int e, int ks, const float* __restrict__ Bp, const float* __restrict__ Tprev,
    const float* __restrict__ Gprev, const int* __restrict__ from,
    uint32_t* hw, uint32_t* lw)
{
    const float* bp = Bp + (size_t)e * EH + ks * 16;
    float4 b0 = *(const float4*)(bp + 0);
    float4 b1 = *(const float4*)(bp + 4);
    float4 b2 = *(const float4*)(bp + 8);
    float4 b3 = *(const float4*)(bp + 12);
    float v[16];
    if constexpr (FIRST) {
        v[0]=fmaxf(b0.x,0.f); v[1]=fmaxf(b0.y,0.f); v[2]=fmaxf(b0.z,0.f); v[3]=fmaxf(b0.w,0.f);
        v[4]=fmaxf(b1.x,0.f); v[5]=fmaxf(b1.y,0.f); v[6]=fmaxf(b1.z,0.f); v[7]=fmaxf(b1.w,0.f);
        v[8]=fmaxf(b2.x,0.f); v[9]=fmaxf(b2.y,0.f); v[10]=fmaxf(b2.z,0.f); v[11]=fmaxf(b2.w,0.f);
        v[12]=fmaxf(b3.x,0.f); v[13]=fmaxf(b3.y,0.f); v[14]=fmaxf(b3.z,0.f); v[15]=fmaxf(b3.w,0.f);
    } else {
        int u = __ldg(&from[e]);
        const float* tp = Tprev + (size_t)u * EH + ks * 16;
        const float* gp = Gprev + (size_t)(e ^ 1) * EH + ks * 16;
        float4 t0 = *(const float4*)(tp + 0);
        float4 t1 = *(const float4*)(tp + 4);
        float4 t2 = *(const float4*)(tp + 8);
        float4 t3 = *(const float4*)(tp + 12);
        float4 g0 = *(const float4*)(gp + 0);
        float4 g1 = *(const float4*)(gp + 4);
        float4 g2 = *(const float4*)(gp + 8);
        float4 g3 = *(const float4*)(gp + 12);
        v[0]=fmaxf(b0.x+t0.x-g0.x,0.f); v[1]=fmaxf(b0.y+t0.y-g0.y,0.f);
        v[2]=fmaxf(b0.z+t0.z-g0.z,0.f); v[3]=fmaxf(b0.w+t0.w-g0.w,0.f);
        v[4]=fmaxf(b1.x+t1.x-g1.x,0.f); v[5]=fmaxf(b1.y+t1.y-g1.y,0.f);
        v[6]=fmaxf(b1.z+t1.z-g1.z,0.f); v[7]=fmaxf(b1.w+t1.w-g1.w,0.f);
        v[8]=fmaxf(b2.x+t2.x-g2.x,0.f); v[9]=fmaxf(b2.y+t2.y-g2.y,0.f);
        v[10]=fmaxf(b2.z+t2.z-g2.z,0.f); v[11]=fmaxf(b2.w+t2.w-g2.w,0.f);
        v[12]=fmaxf(b3.x+t3.x-g3.x,0.f); v[13]=fmaxf(b3.y+t3.y-g3.y,0.f);
        v[14]=fmaxf(b3.z+t3.z-g3.z,0.f); v[15]=fmaxf(b3.w+t3.w-g3.w,0.f);
    }
#pragma unroll
    for (int j = 0; j < 8; ++j)
        tsplit(v[2 * j], v[2 * j + 1], hw[j], lw[j]);
}

template <bool FIRST, bool OUT>
__global__ void __launch_bounds__(256, 2)
gemm_fused(const float* __restrict__ Bp, const float* __restrict__ Tprev,
           const float* __restrict__ Gprev, const uint4* __restrict__ Wg,
           const int* __restrict__ from, const int* __restrict__ scat,
           const float* __restrict__ obias,
           float* __restrict__ Gout, float* __restrict__ Acc,
           float* __restrict__ Zbuf)
{
    extern __shared__ uint4 smem4[];
    uint4* AhP = smem4;
    uint4* AlP = smem4 + A_PLANE;
    uint4* Wp  = smem4 + W_OFF;

    const int tid = threadIdx.x;

    // ---- stage packed W once ----
#pragma unroll
    for (int i = 0; i < 16; ++i) Wp[tid + i * 256] = Wg[tid + i * 256];

    // staging item: (row pair, k-block)
    const int ksI   = tid & 7;
    const int pr    = tid >> 3;        // 0..31
    const int wrmtI = pr >> 3;         // 0..3
    const int gidI  = pr & 7;
    const int raL   = wrmtI * 16 + gidI;
    const int xrI   = ksI & 3;
    const int baseI = ((wrmtI * 8 + ksI) * 8 + gidI) * 4;

    const int wid = tid >> 5, lane = tid & 31;
    const int gid = lane >> 2, tig = lane & 3;
    const int wr = wid & 1, wc = wid >> 1;
    const int ar0 = wr * 32, cn0 = wc * 32;

    float obv[8];
    if constexpr (OUT) {
#pragma unroll
        for (int nt = 0; nt < 4; ++nt) {
            obv[2 * nt]     = obias[cn0 + nt * 8 + tig * 2];
            obv[2 * nt + 1] = obias[cn0 + nt * 8 + tig * 2 + 1];
        }
    }

    for (int t = blockIdx.x; t < NTILE; t += NBLK) {
        const int r0 = t * 64;
        __syncthreads();   // previous MMA reads done

        // ---- stage rows (raL, raL+8), k-block ksI ----
        uint32_t hwa[8], lwa[8], hwb[8], lwb[8];
        stage_row<FIRST>(r0 + raL,     ksI, Bp, Tprev, Gprev, from, hwa, lwa);
        stage_row<FIRST>(r0 + raL + 8, ksI, Bp, Tprev, Gprev, from, hwb, lwb);
#pragma unroll
        for (int q = 0; q < 4; ++q) {
            AhP[baseI + (q ^ xrI)] = make_uint4(hwa[q], hwb[q], hwa[q + 4], hwb[q + 4]);
            AlP[baseI + (q ^ xrI)] = make_uint4(lwa[q], lwb[q], lwa[q + 4], lwb[q + 4]);
        }
        __syncthreads();

        // ---- MMA ----
        float acc[2][4][4];
#pragma unroll
        for (int mt = 0; mt < 2; ++mt)
#pragma unroll
            for (int nt = 0; nt < 4; ++nt)
#pragma unroll
                for (int j = 0; j < 4; ++j) acc[mt][nt][j] = 0.f;

#pragma unroll
        for (int ks = 0; ks < 8; ++ks) {
            const int xr = ks & 3;
            uint4 a_h[2], a_l[2];
#pragma unroll
            for (int mt = 0; mt < 2; ++mt) {
                int ia = (((wr * 2 + mt) * 8 + ks) * 8 + gid) * 4 + (tig ^ xr);
                a_h[mt] = AhP[ia];
                a_l[mt] = AlP[ia];
            }
#pragma unroll
            for (int nt = 0; nt < 4; ++nt) {
                int iw = (((wc * 8 + ks) * 4 + nt) * 8 + gid) * 4 + tig;
                uint4 w4 = Wp[iw];
                // hi*hi + lo*hi + hi*lo  (3xBF16)
                mma16(acc[0][nt], (const uint32_t*)&a_h[0], w4.x, w4.y);
                mma16(acc[1][nt], (const uint32_t*)&a_h[1], w4.x, w4.y);
                mma16(acc[0][nt], (const uint32_t*)&a_l[0], w4.x, w4.y);
                mma16(acc[1][nt], (const uint32_t*)&a_l[1], w4.x, w4.y);
                mma16(acc[0][nt], (const uint32_t*)&a_h[0], w4.z, w4.w);
                mma16(acc[1][nt], (const uint32_t*)&a_h[1], w4.z, w4.w);
            }
        }

        // ---- epilogue (per-warp, independent) ----
#pragma unroll
        for (int mt = 0; mt < 2; ++mt) {
#pragma unroll
            for (int half = 0; half < 2; ++half) {
                const int r  = r0 + ar0 + mt * 16 + gid + half * 8;
                const int sc = __ldg(&scat[r]);
                float* ap = Acc + (size_t)sc * EH;
#pragma unroll
                for (int nt = 0; nt < 4; ++nt) {
                    const int col = cn0 + nt * 8 + tig * 2;
                    float x = acc[mt][nt][half * 2 + 0];
                    float y = acc[mt][nt][half * 2 + 1];
                    if constexpr (OUT) {
                        x += obv[2 * nt]; y += obv[2 * nt + 1];
                    } else {
                        *(float2*)(Gout + (size_t)r * EH + col) = make_float2(x, y);
                    }
                    red2(ap + col, x, y);
                }
            }
        }
    }

    // ---- grid-stride zero of the next step's accumulator / d_out ----
    if (Zbuf != nullptr) {
        const size_t n4 = (size_t)NN * EH / 4;
        float4 z = make_float4(0.f, 0.f, 0.f, 0.f);
        for (size_t i = (size_t)blockIdx.x * 256 + tid; i < n4; i += (size_t)NBLK * 256)
            ((float4*)Zbuf)[i] = z;
    }
}

// ============================================================
// Scalar fp32 GEMM (small precompute GEMMs only).
// blockIdx.y == 1 switches to the alternate (W2/b2/C2) problem.
// ============================================================
template <int KTOT, int EPI>
__global__ void __launch_bounds__(256)
gemm_tile(const float* __restrict__ A, const float* W_, const float* bias_,
          float* C_, int M,
          const int* __restrict__ gidx, const float* __restrict__ gadd,
          const float* W2_, const float* bias2_, float* C2_)
{
    const float* W = (blockIdx.y == 0) ? W_ : W2_;
    const float* bias = (blockIdx.y == 0) ? bias_ : bias2_;
    float* C = (blockIdx.y == 0) ? C_ : C2_;

    constexpr int KC = (KTOT < 32) ? KTOT : 32;
    __shared__ float As[KC][132];
    __shared__ float Ws[KC][128];

    const int tid = threadIdx.x;
    const int tr  = tid >> 4;
    const int tc  = tid & 15;
    const int r0  = blockIdx.x * 128;

    float acc[8][8];
#pragma unroll
    for (int i = 0; i < 8; ++i)
#pragma unroll
        for (int j = 0; j < 8; ++j) acc[i][j] = 0.f;

    for (int kc0 = 0; kc0 < KTOT; kc0 += KC) {
        __syncthreads();
#pragma unroll
        for (int i = 0; i < KC / 8; ++i) {
            int f  = tid + i * 256;
            int r  = f / (KC / 4);
            int c4 = (f % (KC / 4)) * 4;
            float4 v = make_float4(0.f, 0.f, 0.f, 0.f);
            int gr = r0 + r;
            if (gr < M) v = *(const float4*)(A + (size_t)gr * KTOT + kc0 + c4);
            As[c4 + 0][r] = v.x; As[c4 + 1][r] = v.y;
            As[c4 + 2][r] = v.z; As[c4 + 3][r] = v.w;
        }
#pragma unroll
        for (int i = 0; i < KC / 8; ++i) {
            int f  = tid + i * 256;
            int kr = f >> 5;
            int c4 = (f & 31) * 4;
            *(float4*)(&Ws[kr][c4]) = *(const float4*)(W + (size_t)(kc0 + kr) * EH + c4);
        }
        __syncthreads();
#pragma unroll
        for (int k = 0; k < KC; ++k) {
            float a[8], w[8];
            *(float4*)&a[0] = *(const float4*)&As[k][tr * 8];
            *(float4*)&a[4] = *(const float4*)&As[k][tr * 8 + 4];
            *(float4*)&w[0] = *(const float4*)&Ws[k][tc * 8];
            *(float4*)&w[4] = *(const float4*)&Ws[k][tc * 8 + 4];
#pragma unroll
            for (int i = 0; i < 8; ++i)
#pragma unroll
                for (int j = 0; j < 8; ++j) acc[i][j] += a[i] * w[j];
        }
    }

    float bs[8];
#pragma unroll
    for (int j = 0; j < 8; ++j) bs[j] = bias[tc * 8 + j];

    const int c0 = tc * 8;
#pragma unroll
    for (int i = 0; i < 8; ++i) {
        int r = r0 + tr * 8 + i;
        if (r >= M) continue;
        if constexpr (EPI == 0) {
            float4 v0, v1;
            v0.x = acc[i][0] + bs[0]; v0.y = acc[i][1] + bs[1];
            v0.z = acc[i][2] + bs[2]; v0.w = acc[i][3] + bs[3];
            v1.x = acc[i][4] + bs[4]; v1.y = acc[i][5] + bs[5];
            v1.z = acc[i][6] + bs[6]; v1.w = acc[i][7] + bs[7];
            *(float4*)(C + (size_t)r * EH + c0)     = v0;
            *(float4*)(C + (size_t)r * EH + c0 + 4) = v1;
        } else {
            int u = gidx[r];
            const float* gp = gadd + (size_t)u * EH + c0;
            float4 p0 = *(const float4*)gp;
            float4 p1 = *(const float4*)(gp + 4);
            float4 v0, v1;
            v0.x = acc[i][0] + bs[0] + p0.x; v0.y = acc[i][1] + bs[1] + p0.y;
            v0.z = acc[i][2] + bs[2] + p0.z; v0.w = acc[i][3] + bs[3] + p0.w;
            v1.x = acc[i][4] + bs[4] + p1.x; v1.y = acc[i][5] + bs[5] + p1.y;
            v1.z = acc[i][6] + bs[6] + p1.z; v1.w = acc[i][7] + bs[7] + p1.w;
            *(float4*)(C + (size_t)r * EH + c0)     = v0;
            *(float4*)(C + (size_t)r * EH + c0 + 4) = v1;
        }
    }
}

// out = relu(out + U1x)
__global__ void __launch_bounds__(256)
final_relu(float* __restrict__ out, const float* __restrict__ U1x)
{
    int idx = blockIdx.x * blockDim.x + threadIdx.x;
    if (idx >= NN * EH / 4) return;
    float4 a = ((const float4*)out)[idx];
    float4 b = ((const float4*)U1x)[idx];
    float4 r;
    r.x = fmaxf(a.x + b.x, 0.f);
    r.y = fmaxf(a.y + b.y, 0.f);
    r.z = fmaxf(a.z + b.z, 0.f);
    r.w = fmaxf(a.w + b.w, 0.f);
    ((float4*)out)[idx] = r;
}

extern "C" void kernel_launch(void* const* d_in, const int* in_sizes, int n_in,
                              void* d_out, int out_size)
{
    const float* nf  = (const float*)d_in[0];
    const float* ef  = (const float*)d_in[1];
    const int*   edg = (const int*)  d_in[3];
    const float* W1w = (const float*)d_in[4];
    const float* W1b = (const float*)d_in[5];
    const float* W2w = (const float*)d_in[6];
    const float* W2b = (const float*)d_in[7];
    const float* W3w = (const float*)d_in[8];
    const float* W3b = (const float*)d_in[9];
    const float* U1w = (const float*)d_in[10];
    const float* U1b = (const float*)d_in[11];
    const float* U2w = (const float*)d_in[12];
    const float* U2b = (const float*)d_in[13];

    const int* from = edg;
    const int* to   = edg + NE;

    float *P, *U1x, *B, *G0, *G1, *T0, *T1, *T2, *cb;
    uint4 *W3p, *U2p;
    cudaGetSymbolAddress((void**)&P,   g_P);
    cudaGetSymbolAddress((void**)&U1x, g_U1);
    cudaGetSymbolAddress((void**)&B,   g_B);
    cudaGetSymbolAddress((void**)&G0,  g_G0);
    cudaGetSymbolAddress((void**)&G1,  g_G1);
    cudaGetSymbolAddress((void**)&T0,  g_T0);
    cudaGetSymbolAddress((void**)&T1,  g_T1);
    cudaGetSymbolAddress((void**)&T2,  g_T2);
    cudaGetSymbolAddress((void**)&W3p, g_W3p);
    cudaGetSymbolAddress((void**)&U2p, g_U2p);
    cudaGetSymbolAddress((void**)&cb,  g_cb);

    cudaFuncSetAttribute(gemm_fused<true,  false>,
                         cudaFuncAttributeMaxDynamicSharedMemorySize, (int)SM_TOT);
    cudaFuncSetAttribute(gemm_fused<false, false>,
                         cudaFuncAttributeMaxDynamicSharedMemorySize, (int)SM_TOT);
    cudaFuncSetAttribute(gemm_fused<false, true>,
                         cudaFuncAttributeMaxDynamicSharedMemorySize, (int)SM_TOT);

    const int gnode = (NN + 127) / 128;
    const int gedge128 = (NE + 127) / 128;

    // weight prep + combined bias (single launch)
    prep_all<<<33, 256>>>(W3w, U2w, W2b, W3b, W3p, U2p, cb);

    // loop-invariant precomputes: both node GEMMs in ONE launch (y selects set)
    gemm_tile<64, 0><<<dim3(gnode, 2), 256>>>(
        nf, W1w, W1b, P, NN, nullptr, nullptr, U1w, U1b, U1x);
    gemm_tile<16, 1><<<dim3(gedge128, 1), 256>>>(
        ef, W2w, cb, B, NE, from, P, nullptr, nullptr, nullptr);

    // T rotation: step s writes T[s%3], reads T[(s-1)%3], zeroes T[(s+1)%3].
    float* Tb[3] = {T0, T1, T2};
    float* Gb[2] = {G0, G1};

    // initial zero of T1 (step 1's write target)
    cudaMemsetAsync(T1, 0, (size_t)NN * EH * sizeof(float));

    // s = 1: h1 = relu(B'); writes G1, T1; zeroes T2
    gemm_fused<true, false><<<NBLK, 256, SM_TOT>>>(
        B, nullptr, nullptr, W3p, from, from, nullptr, Gb[1], Tb[1], Tb[2]);

    // s = 2..5
    for (int s = 2; s <= 5; ++s) {
        float* zb = (s < 5) ? Tb[(s + 1) % 3] : (float*)d_out;  // s=5 zeroes d_out
        gemm_fused<false, false><<<NBLK, 256, SM_TOT>>>(
            B, Tb[(s - 1) % 3], Gb[(s - 1) & 1], W3p, from, from, nullptr,
            Gb[s & 1], Tb[s % 3], zb);
    }

    // readout: h6 from (T5 = Tb[2], G5 = Gb[1]); red into d_out by `to`
    gemm_fused<false, true><<<NBLK, 256, SM_TOT>>>(
        B, Tb[5 % 3], Gb[5 & 1], U2p, from, to, U2b, nullptr, (float*)d_out,
        nullptr);

    final_relu<<<(NN * EH / 4 + 255) / 256, 256>>>((float*)d_out, U1x);
}

// round 13
// speedup vs baseline: 1.4123x; 1.1421x over previous
#include <cuda_runtime.h>
#include <cuda_bf16.h>
#include <cstdint>
#include <cstddef>

#define NN 100000
#define NE 600000
#define NF 64
#define EF 16
#define EH 128
#define NSTEPS 6
#define NTILE (NE / 64)      // 9375
#define NBLK  148            // 1 CTA per SM, persistent

// ---- scratch (device globals; no allocation allowed) ----
__device__ float g_P  [(size_t)NN * EH];
__device__ float g_U1 [(size_t)NN * EH];
__device__ float g_B  [(size_t)NE * EH];
__device__ float g_G0 [(size_t)NE * EH];
__device__ float g_G1 [(size_t)NE * EH];
__device__ float g_T0 [(size_t)NN * EH];
__device__ float g_T1 [(size_t)NN * EH];
__device__ float g_T2 [(size_t)NN * EH];
__device__ uint4 g_W3p[4096];              // W3^T fragment-packed (bh0,bh1,bl0,bl1)
__device__ uint4 g_U2p[4096];              // U2^T fragment-packed
__device__ float g_cb [EH];                // W2_b + W3_b

// ================= helpers =================
__device__ __forceinline__ void mma16(float* c, const uint32_t* a,
                                      uint32_t b0, uint32_t b1) {
    asm volatile(
        "mma.sync.aligned.m16n8k16.row.col.f32.bf16.bf16.f32 "
        "{%0,%1,%2,%3}, {%4,%5,%6,%7}, {%8,%9}, {%0,%1,%2,%3};"
        : "+f"(c[0]), "+f"(c[1]), "+f"(c[2]), "+f"(c[3])
        : "r"(a[0]), "r"(a[1]), "r"(a[2]), "r"(a[3]), "r"(b0), "r"(b1));
}

__device__ __forceinline__ void red2(float* p, float x, float y) {
    asm volatile("red.global.add.v2.f32 [%0], {%1, %2};"
                 :: "l"(p), "f"(x), "f"(y) : "memory");
}

__device__ __forceinline__ void bar_sync(int id) {
    asm volatile("bar.sync %0, 256;" :: "r"(id) : "memory");
}
__device__ __forceinline__ void bar_arrive(int id) {
    asm volatile("bar.arrive %0, 256;" :: "r"(id) : "memory");
}

// rn-split (prep only)
__device__ __forceinline__ void split2(float x, float y, uint32_t& hi, uint32_t& lo) {
    __nv_bfloat162 h = __floats2bfloat162_rn(x, y);
    float2 hf = __bfloat1622float2(h);
    __nv_bfloat162 l = __floats2bfloat162_rn(x - hf.x, y - hf.y);
    hi = *(uint32_t*)&h;
    lo = *(uint32_t*)&l;
}

// fast truncation split
__device__ __forceinline__ void tsplit(float x, float y, uint32_t& hw, uint32_t& lw) {
    uint32_t xb = __float_as_uint(x), yb = __float_as_uint(y);
    hw = __byte_perm(xb, yb, 0x7632);
    float lx = x - __uint_as_float(xb & 0xFFFF0000u);
    float ly = y - __uint_as_float(yb & 0xFFFF0000u);
    __nv_bfloat162 l2 = __floats2bfloat162_rn(lx, ly);
    lw = *(uint32_t*)&l2;
}

// pack W3^T / U2^T into fragment uint4 layout + combined bias
__global__ void prep_all(const float* __restrict__ W3, const float* __restrict__ U2,
                         const float* __restrict__ W2b, const float* __restrict__ W3b,
                         uint4* __restrict__ W3p, uint4* __restrict__ U2p,
                         float* __restrict__ cb) {
    int b = blockIdx.x, tid = threadIdx.x;
    if (b < 32) {
        const float* W = (b < 16) ? W3 : U2;
        uint4* out = (b < 16) ? W3p : U2p;
        int idx = (b & 15) * 256 + tid;
        int tig = idx & 3, gid = (idx >> 2) & 7, nt = (idx >> 5) & 3;
        int ks = (idx >> 7) & 7, wc = idx >> 10;
        int n = wc * 32 + nt * 8 + gid;
        int kw0 = ks * 8 + tig, kw1 = kw0 + 4;
        uint32_t bh0, bl0, bh1, bl1;
        split2(W[(2 * kw0) * 128 + n], W[(2 * kw0 + 1) * 128 + n], bh0, bl0);
        split2(W[(2 * kw1) * 128 + n], W[(2 * kw1 + 1) * 128 + n], bh1, bl1);
        out[idx] = make_uint4(bh0, bh1, bl0, bl1);
    } else if (b == 32) {
        if (tid < EH) cb[tid] = W2b[tid] + W3b[tid];
    }
}

// ============================================================
// Fused 3xBF16 MMA GEMM — persistent, warp-specialized pipeline.
// Warps 4-7 (producers): stage A tiles (combine+split) double-buffered.
// Warps 0-3 (consumers): MMA + epilogue.
// Named barriers: full_p = 1+p, empty_p = 3+p (counts 256 = 128 arrive + 128 sync).
// ============================================================
static constexpr int BUF_U4 = 2048;                 // uint4 per A buffer (hi+lo)
static constexpr int W_OFF  = 4096;                 // uint4 offset of W
static constexpr size_t SM_TOT = (size_t)(4096 + 4096) * 16;   // 131072 B

template <bool FIRST>
__device__ __forceinline__ void stage_row(
    int e, int u, int ks, const float* __restrict__ Bp,
    const float* __restrict__ Tprev, const float* __restrict__ Gprev,
    uint32_t* hw, uint32_t* lw)
{
    const float* bp = Bp + (size_t)e * EH + ks * 16;
    float4 b0 = *(const float4*)(bp + 0);
    float4 b1 = *(const float4*)(bp + 4);
    float4 b2 = *(const float4*)(bp + 8);
    float4 b3 = *(const float4*)(bp + 12);
    float v[16];
    if constexpr (FIRST) {
        v[0]=fmaxf(b0.x,0.f); v[1]=fmaxf(b0.y,0.f); v[2]=fmaxf(b0.z,0.f); v[3]=fmaxf(b0.w,0.f);
        v[4]=fmaxf(b1.x,0.f); v[5]=fmaxf(b1.y,0.f); v[6]=fmaxf(b1.z,0.f); v[7]=fmaxf(b1.w,0.f);
        v[8]=fmaxf(b2.x,0.f); v[9]=fmaxf(b2.y,0.f); v[10]=fmaxf(b2.z,0.f); v[11]=fmaxf(b2.w,0.f);
        v[12]=fmaxf(b3.x,0.f); v[13]=fmaxf(b3.y,0.f); v[14]=fmaxf(b3.z,0.f); v[15]=fmaxf(b3.w,0.f);
    } else {
        const float* tp = Tprev + (size_t)u * EH + ks * 16;
        const float* gp = Gprev + (size_t)(e ^ 1) * EH + ks * 16;
        float4 t0 = *(const float4*)(tp + 0);
        float4 t1 = *(const float4*)(tp + 4);
        float4 t2 = *(const float4*)(tp + 8);
        float4 t3 = *(const float4*)(tp + 12);
        float4 g0 = *(const float4*)(gp + 0);
        float4 g1 = *(const float4*)(gp + 4);
        float4 g2 = *(const float4*)(gp + 8);
        float4 g3 = *(const float4*)(gp + 12);
        v[0]=fmaxf(b0.x+t0.x-g0.x,0.f); v[1]=fmaxf(b0.y+t0.y-g0.y,0.f);
        v[2]=fmaxf(b0.z+t0.z-g0.z,0.f); v[3]=fmaxf(b0.w+t0.w-g0.w,0.f);
        v[4]=fmaxf(b1.x+t1.x-g1.x,0.f); v[5]=fmaxf(b1.y+t1.y-g1.y,0.f);
        v[6]=fmaxf(b1.z+t1.z-g1.z,0.f); v[7]=fmaxf(b1.w+t1.w-g1.w,0.f);
        v[8]=fmaxf(b2.x+t2.x-g2.x,0.f); v[9]=fmaxf(b2.y+t2.y-g2.y,0.f);
        v[10]=fmaxf(b2.z+t2.z-g2.z,0.f); v[11]=fmaxf(b2.w+t2.w-g2.w,0.f);
        v[12]=fmaxf(b3.x+t3.x-g3.x,0.f); v[13]=fmaxf(b3.y+t3.y-g3.y,0.f);
        v[14]=fmaxf(b3.z+t3.z-g3.z,0.f); v[15]=fmaxf(b3.w+t3.w-g3.w,0.f);
    }
#pragma unroll
    for (int j = 0; j < 8; ++j)
        tsplit(v[2 * j], v[2 * j + 1], hw[j], lw[j]);
}

template <bool FIRST, bool OUT>
__global__ void __launch_bounds__(256, 1)
gemm_fused(const float* __restrict__ Bp, const float* __restrict__ Tprev,
           const float* __restrict__ Gprev, const uint4* __restrict__ Wg,
           const int* __restrict__ from, const int* __restrict__ scat,
           const float* __restrict__ obias,
           float* __restrict__ Gout, float* __restrict__ Acc,
           float* __restrict__ Zbuf)
{
    extern __shared__ uint4 smem4[];
    uint4* Wp = smem4 + W_OFF;

    const int tid = threadIdx.x;
    const int wid = tid >> 5;

    // ---- stage packed W once (all threads) ----
#pragma unroll
    for (int i = 0; i < 16; ++i) Wp[tid + i * 256] = Wg[tid + i * 256];
    __syncthreads();

    if (wid >= 4) {
        // ================= PRODUCER (warps 4-7) =================
        const int ptid = tid - 128;
        // two items per thread: it0 = ptid, it1 = ptid + 128
        const int ks0 = ptid & 7,        pr0 = ptid >> 3;
        const int wm0 = pr0 >> 3,        gd0 = pr0 & 7;
        const int ra0 = wm0 * 16 + gd0;
        const int xr0 = ks0 & 3;
        const int bs0 = ((wm0 * 8 + ks0) * 8 + gd0) * 4;
        const int it1 = ptid + 128;
        const int ks1 = it1 & 7,         pr1 = it1 >> 3;
        const int wm1 = pr1 >> 3,        gd1 = pr1 & 7;
        const int ra1 = wm1 * 16 + gd1;
        const int xr1 = ks1 & 3;
        const int bs1 = ((wm1 * 8 + ks1) * 8 + gd1) * 4;

        int i = 0;
        for (int t = blockIdx.x; t < NTILE; t += NBLK, ++i) {
            const int p = i & 1;
            if (i >= 2) bar_sync(3 + p);
            uint4* AhP = smem4 + p * BUF_U4;
            uint4* AlP = AhP + 1024;
            const int r0 = t * 64;

            const int eA = r0 + ra0, eB = eA + 8;
            const int eC = r0 + ra1, eD = eC + 8;
            int uA = 0, uB = 0, uC = 0, uD = 0;
            if constexpr (!FIRST) {
                uA = __ldg(&from[eA]); uB = __ldg(&from[eB]);
                uC = __ldg(&from[eC]); uD = __ldg(&from[eD]);
            }
            uint32_t hwa[8], lwa[8], hwb[8], lwb[8];
            stage_row<FIRST>(eA, uA, ks0, Bp, Tprev, Gprev, hwa, lwa);
            stage_row<FIRST>(eB, uB, ks0, Bp, Tprev, Gprev, hwb, lwb);
#pragma unroll
            for (int q = 0; q < 4; ++q) {
                AhP[bs0 + (q ^ xr0)] = make_uint4(hwa[q], hwb[q], hwa[q + 4], hwb[q + 4]);
                AlP[bs0 + (q ^ xr0)] = make_uint4(lwa[q], lwb[q], lwa[q + 4], lwb[q + 4]);
            }
            stage_row<FIRST>(eC, uC, ks1, Bp, Tprev, Gprev, hwa, lwa);
            stage_row<FIRST>(eD, uD, ks1, Bp, Tprev, Gprev, hwb, lwb);
#pragma unroll
            for (int q = 0; q < 4; ++q) {
                AhP[bs1 + (q ^ xr1)] = make_uint4(hwa[q], hwb[q], hwa[q + 4], hwb[q + 4]);
                AlP[bs1 + (q ^ xr1)] = make_uint4(lwa[q], lwb[q], lwa[q + 4], lwb[q + 4]);
            }
            bar_arrive(1 + p);
        }
    } else {
        // ================= CONSUMER (warps 0-3) =================
        const int lane = tid & 31;
        const int gid = lane >> 2, tig = lane & 3;
        const int wr = wid & 1, wc2 = wid >> 1;       // 2 row groups x 2 col groups
        const int ar0 = wr * 32, cn0 = wc2 * 64;

        float obv[16];
        if constexpr (OUT) {
#pragma unroll
            for (int nt = 0; nt < 8; ++nt) {
                obv[2 * nt]     = obias[cn0 + nt * 8 + tig * 2];
                obv[2 * nt + 1] = obias[cn0 + nt * 8 + tig * 2 + 1];
            }
        }

        int i = 0;
        for (int t = blockIdx.x; t < NTILE; t += NBLK, ++i) {
            const int p = i & 1;
            bar_sync(1 + p);
            const uint4* AhP = smem4 + p * BUF_U4;
            const uint4* AlP = AhP + 1024;
            const int r0 = t * 64;

            float acc[2][8][4];
#pragma unroll
            for (int mt = 0; mt < 2; ++mt)
#pragma unroll
                for (int nt = 0; nt < 8; ++nt)
#pragma unroll
                    for (int j = 0; j < 4; ++j) acc[mt][nt][j] = 0.f;

#pragma unroll
            for (int ks = 0; ks < 8; ++ks) {
                const int xr = ks & 3;
                uint4 a_h[2], a_l[2];
#pragma unroll
                for (int mt = 0; mt < 2; ++mt) {
                    int ia = (((wr * 2 + mt) * 8 + ks) * 8 + gid) * 4 + (tig ^ xr);
                    a_h[mt] = AhP[ia];
                    a_l[mt] = AlP[ia];
                }
#pragma unroll
                for (int nt = 0; nt < 8; ++nt) {
                    const int wpk = wc2 * 2 + (nt >> 2);
                    const int ntp = nt & 3;
                    const int iw = ((wpk * 8 + ks) * 4 + ntp) * 32 + gid * 4 + tig;
                    uint4 w4 = Wp[iw];
                    mma16(acc[0][nt], (const uint32_t*)&a_h[0], w4.x, w4.y);
                    mma16(acc[1][nt], (const uint32_t*)&a_h[1], w4.x, w4.y);
                    mma16(acc[0][nt], (const uint32_t*)&a_l[0], w4.x, w4.y);
                    mma16(acc[1][nt], (const uint32_t*)&a_l[1], w4.x, w4.y);
                    mma16(acc[0][nt], (const uint32_t*)&a_h[0], w4.z, w4.w);
                    mma16(acc[1][nt], (const uint32_t*)&a_h[1], w4.z, w4.w);
                }
            }
            bar_arrive(3 + p);   // buffer free — epilogue is register-only

            // ---- epilogue ----
#pragma unroll
            for (int mt = 0; mt < 2; ++mt) {
#pragma unroll
                for (int half = 0; half < 2; ++half) {
                    const int r  = r0 + ar0 + mt * 16 + gid + half * 8;
                    const int sc = __ldg(&scat[r]);
                    float* ap = Acc + (size_t)sc * EH;
#pragma unroll
                    for (int nt = 0; nt < 8; ++nt) {
                        const int col = cn0 + nt * 8 + tig * 2;
                        float x = acc[mt][nt][half * 2 + 0];
                        float y = acc[mt][nt][half * 2 + 1];
                        if constexpr (OUT) {
                            x += obv[2 * nt]; y += obv[2 * nt + 1];
                        } else {
                            *(float2*)(Gout + (size_t)r * EH + col) = make_float2(x, y);
                        }
                        red2(ap + col, x, y);
                    }
                }
            }
        }
    }

    // ---- grid-stride zero of the next step's accumulator / d_out ----
    if (Zbuf != nullptr) {
        const size_t n4 = (size_t)NN * EH / 4;
        float4 z = make_float4(0.f, 0.f, 0.f, 0.f);
        for (size_t i = (size_t)blockIdx.x * 256 + tid; i < n4; i += (size_t)NBLK * 256)
            ((float4*)Zbuf)[i] = z;
    }
}

// ============================================================
// Scalar fp32 GEMM (small precompute GEMMs only).
// blockIdx.y == 1 switches to the alternate (W2/b2/C2) problem.
// ============================================================
template <int KTOT, int EPI>
__global__ void __launch_bounds__(256)
gemm_tile(const float* __restrict__ A, const float* W_, const float* bias_,
          float* C_, int M,
          const int* __restrict__ gidx, const float* __restrict__ gadd,
          const float* W2_, const float* bias2_, float* C2_)
{
    const float* W = (blockIdx.y == 0) ? W_ : W2_;
    const float* bias = (blockIdx.y == 0) ? bias_ : bias2_;
    float* C = (blockIdx.y == 0) ? C_ : C2_;

    constexpr int KC = (KTOT < 32) ? KTOT : 32;
    __shared__ float As[KC][132];
    __shared__ float Ws[KC][128];

    const int tid = threadIdx.x;
    const int tr  = tid >> 4;
    const int tc  = tid & 15;
    const int r0  = blockIdx.x * 128;

    float acc[8][8];
#pragma unroll
    for (int i = 0; i < 8; ++i)
#pragma unroll
        for (int j = 0; j < 8; ++j) acc[i][j] = 0.f;

    for (int kc0 = 0; kc0 < KTOT; kc0 += KC) {
        __syncthreads();
#pragma unroll
        for (int i = 0; i < KC / 8; ++i) {
            int f  = tid + i * 256;
            int r  = f / (KC / 4);
            int c4 = (f % (KC / 4)) * 4;
            float4 v = make_float4(0.f, 0.f, 0.f, 0.f);
            int gr = r0 + r;
            if (gr < M) v = *(const float4*)(A + (size_t)gr * KTOT + kc0 + c4);
            As[c4 + 0][r] = v.x; As[c4 + 1][r] = v.y;
            As[c4 + 2][r] = v.z; As[c4 + 3][r] = v.w;
        }
#pragma unroll
        for (int i = 0; i < KC / 8; ++i) {
            int f  = tid + i * 256;
            int kr = f >> 5;
            int c4 = (f & 31) * 4;
            *(float4*)(&Ws[kr][c4]) = *(const float4*)(W + (size_t)(kc0 + kr) * EH + c4);
        }
        __syncthreads();
#pragma unroll
        for (int k = 0; k < KC; ++k) {
            float a[8], w[8];
            *(float4*)&a[0] = *(const float4*)&As[k][tr * 8];
            *(float4*)&a[4] = *(const float4*)&As[k][tr * 8 + 4];
            *(float4*)&w[0] = *(const float4*)&Ws[k][tc * 8];
            *(float4*)&w[4] = *(const float4*)&Ws[k][tc * 8 + 4];
#pragma unroll
            for (int i = 0; i < 8; ++i)
#pragma unroll
                for (int j = 0; j < 8; ++j) acc[i][j] += a[i] * w[j];
        }
    }

    float bs[8];
#pragma unroll
    for (int j = 0; j < 8; ++j) bs[j] = bias[tc * 8 + j];

    const int c0 = tc * 8;
#pragma unroll
    for (int i = 0; i < 8; ++i) {
        int r = r0 + tr * 8 + i;
        if (r >= M) continue;
        if constexpr (EPI == 0) {
            float4 v0, v1;
            v0.x = acc[i][0] + bs[0]; v0.y = acc[i][1] + bs[1];
            v0.z = acc[i][2] + bs[2]; v0.w = acc[i][3] + bs[3];
            v1.x = acc[i][4] + bs[4]; v1.y = acc[i][5] + bs[5];
            v1.z = acc[i][6] + bs[6]; v1.w = acc[i][7] + bs[7];
            *(float4*)(C + (size_t)r * EH + c0)     = v0;
            *(float4*)(C + (size_t)r * EH + c0 + 4) = v1;
        } else {
            int u = gidx[r];
            const float* gp = gadd + (size_t)u * EH + c0;
            float4 p0 = *(const float4*)gp;
            float4 p1 = *(const float4*)(gp + 4);
            float4 v0, v1;
            v0.x = acc[i][0] + bs[0] + p0.x; v0.y = acc[i][1] + bs[1] + p0.y;
            v0.z = acc[i][2] + bs[2] + p0.z; v0.w = acc[i][3] + bs[3] + p0.w;
            v1.x = acc[i][4] + bs[4] + p1.x; v1.y = acc[i][5] + bs[5] + p1.y;
            v1.z = acc[i][6] + bs[6] + p1.z; v1.w = acc[i][7] + bs[7] + p1.w;
            *(float4*)(C + (size_t)r * EH + c0)     = v0;
            *(float4*)(C + (size_t)r * EH + c0 + 4) = v1;
        }
    }
}

// out = relu(out + U1x)
__global__ void __launch_bounds__(256)
final_relu(float* __restrict__ out, const float* __restrict__ U1x)
{
    int idx = blockIdx.x * blockDim.x + threadIdx.x;
    if (idx >= NN * EH / 4) return;
    float4 a = ((const float4*)out)[idx];
    float4 b = ((const float4*)U1x)[idx];
    float4 r;
    r.x = fmaxf(a.x + b.x, 0.f);
    r.y = fmaxf(a.y + b.y, 0.f);
    r.z = fmaxf(a.z + b.z, 0.f);
    r.w = fmaxf(a.w + b.w, 0.f);
    ((float4*)out)[idx] = r;
}

extern "C" void kernel_launch(void* const* d_in, const int* in_sizes, int n_in,
                              void* d_out, int out_size)
{
    const float* nf  = (const float*)d_in[0];
    const float* ef  = (const float*)d_in[1];
    const int*   edg = (const int*)  d_in[3];
    const float* W1w = (const float*)d_in[4];
    const float* W1b = (const float*)d_in[5];
    const float* W2w = (const float*)d_in[6];
    const float* W2b = (const float*)d_in[7];
    const float* W3w = (const float*)d_in[8];
    const float* W3b = (const float*)d_in[9];
    const float* U1w = (const float*)d_in[10];
    const float* U1b = (const float*)d_in[11];
    const float* U2w = (const float*)d_in[12];
    const float* U2b = (const float*)d_in[13];

    const int* from = edg;
    const int* to   = edg + NE;

    float *P, *U1x, *B, *G0, *G1, *T0, *T1, *T2, *cb;
    uint4 *W3p, *U2p;
    cudaGetSymbolAddress((void**)&P,   g_P);
    cudaGetSymbolAddress((void**)&U1x, g_U1);
    cudaGetSymbolAddress((void**)&B,   g_B);
    cudaGetSymbolAddress((void**)&G0,  g_G0);
    cudaGetSymbolAddress((void**)&G1,  g_G1);
    cudaGetSymbolAddress((void**)&T0,  g_T0);
    cudaGetSymbolAddress((void**)&T1,  g_T1);
    cudaGetSymbolAddress((void**)&T2,  g_T2);
    cudaGetSymbolAddress((void**)&W3p, g_W3p);
    cudaGetSymbolAddress((void**)&U2p, g_U2p);
    cudaGetSymbolAddress((void**)&cb,  g_cb);

    cudaFuncSetAttribute(gemm_fused<true,  false>,
                         cudaFuncAttributeMaxDynamicSharedMemorySize, (int)SM_TOT);
    cudaFuncSetAttribute(gemm_fused<false, false>,
                         cudaFuncAttributeMaxDynamicSharedMemorySize, (int)SM_TOT);
    cudaFuncSetAttribute(gemm_fused<false, true>,
                         cudaFuncAttributeMaxDynamicSharedMemorySize, (int)SM_TOT);

    const int gnode = (NN + 127) / 128;
    const int gedge128 = (NE + 127) / 128;

    // weight prep + combined bias (single launch)
    prep_all<<<33, 256>>>(W3w, U2w, W2b, W3b, W3p, U2p, cb);

    // loop-invariant precomputes: both node GEMMs in ONE launch (y selects set)
    gemm_tile<64, 0><<<dim3(gnode, 2), 256>>>(
        nf, W1w, W1b, P, NN, nullptr, nullptr, U1w, U1b, U1x);
    gemm_tile<16, 1><<<dim3(gedge128, 1), 256>>>(
        ef, W2w, cb, B, NE, from, P, nullptr, nullptr, nullptr);

    // T rotation: step s writes T[s%3], reads T[(s-1)%3], zeroes T[(s+1)%3].
    float* Tb[3] = {T0, T1, T2};
    float* Gb[2] = {G0, G1};

    cudaMemsetAsync(T1, 0, (size_t)NN * EH * sizeof(float));

    // s = 1: h1 = relu(B'); writes G1, T1; zeroes T2
    gemm_fused<true, false><<<NBLK, 256, SM_TOT>>>(
        B, nullptr, nullptr, W3p, from, from, nullptr, Gb[1], Tb[1], Tb[2]);

    // s = 2..5
    for (int s = 2; s <= 5; ++s) {
        float* zb = (s < 5) ? Tb[(s + 1) % 3] : (float*)d_out;  // s=5 zeroes d_out
        gemm_fused<false, false><<<NBLK, 256, SM_TOT>>>(
            B, Tb[(s - 1) % 3], Gb[(s - 1) & 1], W3p, from, from, nullptr,
            Gb[s & 1], Tb[s % 3], zb);
    }

    // readout: h6 from (T5 = Tb[2], G5 = Gb[1]); red into d_out by `to`
    gemm_fused<false, true><<<NBLK, 256, SM_TOT>>>(
        B, Tb[5 % 3], Gb[5 & 1], U2p, from, to, U2b, nullptr, (float*)d_out,
        nullptr);

    final_relu<<<(NN * EH / 4 + 255) / 256, 256>>>((float*)d_out, U1x);
}